// round 9
// baseline (speedup 1.0000x reference)
#include <cuda_runtime.h>
#include <cstdint>
#include <math.h>

// ---------------------------------------------------------------------------
// TConvDRAW: B=128, NZ=64, NCL=NCC=NCS=128, NA=8, ZH=16, STEPS=6
// tf32 mma.sync conv, cp.async double-buffered pipeline, 64-cout CTA tile.
// ---------------------------------------------------------------------------

#define PIX   256
#define BATCH 128
#define STEPS 6

// scratch offsets (floats)
#define OFF_STATIC_Q 0u
#define OFF_STATIC_P 16777216u
#define OFF_GATES    33554432u
#define OFF_CP       50331648u
#define OFF_CQ       54525952u
#define OFF_RQ       58720256u
#define OFF_RP       62914560u
#define OFF_Z        67108864u
#define OFF_KLB      69206016u
#define OFF_LPQB     69206144u
#define OFF_PW_SSM   69206272u
#define OFF_PW_Q     73404672u
#define OFF_PW_P     80060672u
#define OFF_PW_RQ    85897472u
#define OFF_PW_RP    86307072u
#define OFF_PAD_C    86716672u
#define OFF_PAD_D    97202432u
#define OFF_PAD_A    107688192u
#define OFF_PAD_STMO 108343552u
#define OFF_PAD_ZTMO 118829312u
#define OFF_PAD_ST   124072192u
#define OFF_PAD_HP   134557952u
#define OFF_PAD_HQ   145043712u
#define OFF_PAD_ZB   155529472u
#define SCRATCH_N    160772352u

// pad_st + pad_hp + pad_hq + pad_zb, in floats
#define PAD_STATE_FLOATS 36700160u

__device__ float g_scratch[SCRATCH_N];

__device__ __forceinline__ float to_tf32(float x) {
    uint32_t y;
    asm("cvt.rna.tf32.f32 %0, %1;" : "=r"(y) : "f"(x));
    return __uint_as_float(y);
}

__device__ __forceinline__ void mma_tf32(float& c0, float& c1, float& c2, float& c3,
                                         float a0, float a1, float a2, float a3,
                                         float b0, float b1) {
    asm volatile(
        "mma.sync.aligned.m16n8k8.row.col.f32.tf32.tf32.f32 "
        "{%0,%1,%2,%3}, {%4,%5,%6,%7}, {%8,%9}, {%0,%1,%2,%3};"
        : "+f"(c0), "+f"(c1), "+f"(c2), "+f"(c3)
        : "r"(__float_as_uint(a0)), "r"(__float_as_uint(a1)),
          "r"(__float_as_uint(a2)), "r"(__float_as_uint(a3)),
          "r"(__float_as_uint(b0)), "r"(__float_as_uint(b1)));
}

__device__ __forceinline__ void cpasync16(uint32_t s, const void* g) {
    asm volatile("cp.async.cg.shared.global [%0], [%1], 16;" :: "r"(s), "l"(g));
}
__device__ __forceinline__ void cpcommit() {
    asm volatile("cp.async.commit_group;");
}

// ---------------------------------------------------------------------------
// Combined repack: all 5 weight tensors in ONE launch.
// PW layout per (cg64, chunk): [tap25][mpack4][lane32][slot4] = 12800 floats.
// ---------------------------------------------------------------------------
struct RepackJobs {
    const float* src[5];
    float* dst[5];
    int cinTot[5];
    int nChunks[5];
    int start[6];
};

__global__ void repack_all_kernel(RepackJobs J) {
    int idx = blockIdx.x * 256 + threadIdx.x;
    if (idx >= J.start[5]) return;
    int j = 0;
    while (idx >= J.start[j + 1]) ++j;
    int local = idx - J.start[j];
    int d       = local % 12800;
    int cgchunk = local / 12800;
    int chunk   = cgchunk % J.nChunks[j];
    int cg      = cgchunk / J.nChunks[j];
    int slot = d & 3;
    int lane = (d >> 2) & 31;
    int mp   = (d >> 7) & 3;
    int tap  = d >> 9;
    int co = cg * 64 + mp * 16 + ((slot & 1) << 3) + (lane >> 2);
    int ci = chunk * 8 + (lane & 3) + ((slot >> 1) << 2);
    J.dst[j][local] = to_tf32(J.src[j][((size_t)co * J.cinTot[j] + ci) * 25 + tap]);
}

// ---------------------------------------------------------------------------
// Combined padify: all 5 inputs in ONE launch.
// [planes,256] -> padded tf32 [planes,640] (20 rows x 32 cols, halo=0)
// ---------------------------------------------------------------------------
struct PadJobs {
    const float* src[5];
    float* dst[5];
    int start[6];   // element (not plane) boundaries
};

__global__ void padify_all_kernel(PadJobs J) {
    int idx = blockIdx.x * 256 + threadIdx.x;
    if (idx >= J.start[5]) return;
    int j = 0;
    while (idx >= J.start[j + 1]) ++j;
    int local = idx - J.start[j];
    int plane = local / 640;
    int pp    = local - plane * 640;
    int row = pp >> 5, col = pp & 31;
    float v = 0.f;
    if ((unsigned)(row - 2) < 16u && (unsigned)(col - 2) < 16u)
        v = to_tf32(J.src[j][plane * 256 + (row - 2) * 16 + (col - 2)]);
    J.dst[j][local] = v;
}

// ---------------------------------------------------------------------------
struct Seg { const float* pad; int cin; int chunkBase; };
struct ConvArgs {
    Seg seg[4];
    int nseg;
    const float* PW;
    int nChunks;
    const float* bias;
    const float* base;
    float* out;
    int cout;
};

// buffer: weights 12800 floats + planes 8*648 = 5184 floats
#define BUF_FLOATS 17984
#define CONV_SMEM_BYTES (2 * BUF_FLOATS * 4)   // 143872

// 64 couts x 256 pixels per CTA; 8 warps, each warp: 64 couts x 32 pixels.
__global__ void __launch_bounds__(256, 1) conv5x5_mma_kernel(ConvArgs a) {
    extern __shared__ float smem[];

    const int b    = blockIdx.y;
    const int cg   = blockIdx.x;
    const int tid  = threadIdx.x;
    const int lane = tid & 31;
    const int warp = tid >> 5;
    const int tig  = lane & 3;
    const int g    = lane >> 2;

    int bB[4];
#pragma unroll
    for (int n = 0; n < 4; ++n) {
        int p  = warp * 32 + n * 8;
        bB[n] = (p >> 4) * 32 + (p & 15) + g;
    }

    float acc[4][4][4];
#pragma unroll
    for (int m = 0; m < 4; ++m)
#pragma unroll
        for (int n = 0; n < 4; ++n)
#pragma unroll
            for (int k = 0; k < 4; ++k) acc[m][n][k] = 0.f;

    int total = 0;
    for (int s = 0; s < a.nseg; ++s) total += a.seg[s].cin >> 3;

    const uint32_t smemBase = (uint32_t)__cvta_generic_to_shared(smem);

#define ISSUE(S, C8, BI) do {                                                   \
        const uint32_t dw = smemBase + (BI) * (BUF_FLOATS * 4);                 \
        const uint32_t dp = dw + 12800 * 4;                                     \
        const float* pw = a.PW +                                                \
            (size_t)(cg * a.nChunks + a.seg[S].chunkBase + (C8)) * 12800;       \
        for (int j = tid; j < 3200; j += 256)                                   \
            cpasync16(dw + j * 16, pw + j * 4);                                 \
        const float* sp = a.seg[S].pad +                                        \
            ((size_t)b * a.seg[S].cin + (C8) * 8) * 640;                        \
        for (int j = tid; j < 1280; j += 256) {                                 \
            int ci = j / 160, r = j - ci * 160;                                 \
            cpasync16(dp + ci * 2592 + r * 16, sp + ci * 640 + r * 4);          \
        }                                                                       \
    } while (0)

    int s = 0, c8 = 0;
    ISSUE(s, c8, 0);
    cpcommit();

    for (int i = 0; i < total; ++i) {
        int sn = s, cn = c8 + 1;
        if (cn == (a.seg[sn].cin >> 3)) { cn = 0; ++sn; }
        if (i + 1 < total) ISSUE(sn, cn, (i + 1) & 1);
        cpcommit();
        asm volatile("cp.async.wait_group 1;");
        __syncthreads();

        const float*  swb = smem + (i & 1) * BUF_FLOATS;
        const float*  plb = swb + 12800;
        const float4* swv = (const float4*)swb;
        const float*  pl0 = plb + tig * 648;
        const float*  pl1 = plb + (tig + 4) * 648;

#pragma unroll
        for (int dy = 0; dy < 5; ++dy) {
#pragma unroll
            for (int dx = 0; dx < 5; ++dx) {
                const int tap = dy * 5 + dx;
                float4 A[4];
#pragma unroll
                for (int mp = 0; mp < 4; ++mp)
                    A[mp] = swv[(tap * 4 + mp) * 32 + lane];
                const int off = dy * 32 + dx;
#pragma unroll
                for (int n = 0; n < 4; ++n) {
                    const float b0 = pl0[bB[n] + off];
                    const float b1 = pl1[bB[n] + off];
#pragma unroll
                    for (int mp = 0; mp < 4; ++mp)
                        mma_tf32(acc[mp][n][0], acc[mp][n][1], acc[mp][n][2], acc[mp][n][3],
                                 A[mp].x, A[mp].y, A[mp].z, A[mp].w, b0, b1);
                }
            }
        }
        __syncthreads();
        s = sn; c8 = cn;
    }
#undef ISSUE

    // epilogue
    const int coBase = cg * 64;
#pragma unroll
    for (int mp = 0; mp < 4; ++mp) {
        const int row0 = coBase + mp * 16 + g;
        const int row1 = row0 + 8;
        const float bias0 = a.bias ? a.bias[row0] : 0.f;
        const float bias1 = a.bias ? a.bias[row1] : 0.f;
#pragma unroll
        for (int n = 0; n < 4; ++n) {
            const int col = warp * 32 + n * 8 + 2 * tig;
            size_t o0 = ((size_t)b * a.cout + row0) * PIX + col;
            size_t o1 = ((size_t)b * a.cout + row1) * PIX + col;
            float v0 = acc[mp][n][0] + bias0;
            float v1 = acc[mp][n][1] + bias0;
            float v2 = acc[mp][n][2] + bias1;
            float v3 = acc[mp][n][3] + bias1;
            if (a.base) {
                v0 += a.base[o0];     v1 += a.base[o0 + 1];
                v2 += a.base[o1];     v3 += a.base[o1 + 1];
            }
            a.out[o0]     = v0;
            a.out[o0 + 1] = v1;
            a.out[o1]     = v2;
            a.out[o1 + 1] = v3;
        }
    }
}

// ---------------------------------------------------------------------------
__device__ __forceinline__ float sigmoidf_(float x) { return 1.f / (1.f + expf(-x)); }

__global__ void lstm_kernel(const float* __restrict__ gates,
                            const float* __restrict__ c_in,
                            float* __restrict__ h_exact,
                            float* __restrict__ h_pad,
                            float* __restrict__ c_out) {
    int idx = blockIdx.x * blockDim.x + threadIdx.x;
    if (idx >= 4194304) return;
    int b = idx >> 15;
    int r = idx & 32767;
    size_t g0 = (size_t)b * 131072 + r;
    float ig = gates[g0];
    float fg = gates[g0 + 32768];
    float og = gates[g0 + 65536];
    float gg = gates[g0 + 98304];
    float c  = sigmoidf_(fg) * c_in[idx] + sigmoidf_(ig) * tanhf(gg);
    c_out[idx] = c;
    float h = sigmoidf_(og) * tanhf(c);
    if (h_exact) h_exact[idx] = h;
    int ch = r >> 8, pix = r & 255;
    int row = pix >> 4, col = pix & 15;
    h_pad[((size_t)(b * 128 + ch)) * 640 + (row + 2) * 32 + (col + 2)] = to_tf32(h);
}

// ---------------------------------------------------------------------------
__global__ void zkl_kernel(const float* __restrict__ rq,
                           const float* __restrict__ rp,
                           const float* __restrict__ eps_t,
                           float* __restrict__ z,
                           float* __restrict__ z_pad,
                           float* __restrict__ klb,
                           float* __restrict__ lpqb) {
    const int b = blockIdx.x;
    const int tid = threadIdx.x;
    const float* rqb = rq + (size_t)b * 32768;
    const float* rpb = rp + (size_t)b * 32768;
    const float* eb  = eps_t + (size_t)b * 16384;
    float* zb = z + (size_t)b * 16384;

    float kl = 0.f, lpq = 0.f;
    for (int i = tid; i < 16384; i += 256) {
        float mq = rqb[i], lq = rqb[i + 16384];
        float mp = rpb[i], lp = rpb[i + 16384];
        float e  = eb[i];
        float zi = mq + expf(0.5f * lq) * e;
        zb[i] = zi;
        int ch = i >> 8, pix = i & 255;
        int row = pix >> 4, col = pix & 15;
        z_pad[((size_t)(b * 64 + ch)) * 640 + (row + 2) * 32 + (col + 2)] = to_tf32(zi);
        float dq = zi - mq, dp = zi - mp;
        lpq += 0.5f * ((lq + dq * dq * expf(-lq)) - (lp + dp * dp * expf(-lp)));
        float dm = mq - mp;
        kl  += 0.5f * (lp - lq + (expf(lq) + dm * dm) * expf(-lp) - 1.f);
    }
    __shared__ float s1[256], s2[256];
    s1[tid] = kl; s2[tid] = lpq;
    __syncthreads();
    for (int o = 128; o > 0; o >>= 1) {
        if (tid < o) { s1[tid] += s1[tid + o]; s2[tid] += s2[tid + o]; }
        __syncthreads();
    }
    if (tid == 0) { klb[b] += s1[0]; lpqb[b] += s2[0]; }
}

// ---------------------------------------------------------------------------
__global__ void copy_kernel(const float* __restrict__ src, float* __restrict__ dst, int n) {
    int i = blockIdx.x * blockDim.x + threadIdx.x;
    if (i < n) dst[i] = src[i];
}

__global__ void finalize_kernel(const float* __restrict__ klb,
                                const float* __restrict__ lpqb,
                                float* __restrict__ out_kl,
                                float* __restrict__ out_lpq) {
    __shared__ float s[128];
    int t = threadIdx.x;
    s[t] = klb[t];
    out_lpq[t] = lpqb[t];
    __syncthreads();
    for (int o = 64; o > 0; o >>= 1) {
        if (t < o) s[t] += s[t + o];
        __syncthreads();
    }
    if (t == 0) out_kl[0] = s[0] / 128.f;
}

// ---------------------------------------------------------------------------
static void launch_conv(const Seg* segs, int nseg, const float* PW, int nChunks,
                        const float* bias, const float* base, float* out, int cout) {
    ConvArgs a;
    for (int i = 0; i < 4; ++i) { a.seg[i].pad = nullptr; a.seg[i].cin = 0; a.seg[i].chunkBase = 0; }
    for (int i = 0; i < nseg; ++i) a.seg[i] = segs[i];
    a.nseg = nseg; a.PW = PW; a.nChunks = nChunks;
    a.bias = bias; a.base = base; a.out = out; a.cout = cout;
    dim3 grid(cout / 64, BATCH);
    conv5x5_mma_kernel<<<grid, 256, CONV_SMEM_BYTES>>>(a);
}

extern "C" void kernel_launch(void* const* d_in, const int* in_sizes, int n_in,
                              void* d_out, int out_size) {
    (void)in_sizes; (void)n_in; (void)out_size;
    const float* C_t    = (const float*)d_in[0];
    const float* D_t    = (const float*)d_in[1];
    const float* a_tmo  = (const float*)d_in[2];
    const float* s_tmo  = (const float*)d_in[3];
    const float* c_ssm_tmo = (const float*)d_in[4];
    const float* z_tmo  = (const float*)d_in[5];
    const float* eps    = (const float*)d_in[6];
    const float* W_ssm  = (const float*)d_in[7];
    const float* b_ssm  = (const float*)d_in[8];
    const float* W_p    = (const float*)d_in[9];
    const float* b_p    = (const float*)d_in[10];
    const float* W_q    = (const float*)d_in[11];
    const float* b_q    = (const float*)d_in[12];
    const float* W_rp   = (const float*)d_in[13];
    const float* b_rp   = (const float*)d_in[14];
    const float* W_rq   = (const float*)d_in[15];
    const float* b_rq   = (const float*)d_in[16];

    static int smem_set = -1;
    if (smem_set < 0) {
        cudaFuncSetAttribute(conv5x5_mma_kernel,
                             cudaFuncAttributeMaxDynamicSharedMemorySize, CONV_SMEM_BYTES);
        smem_set = 1;
    }

    float* S;
    cudaGetSymbolAddress((void**)&S, g_scratch);
    float* static_q = S + OFF_STATIC_Q;
    float* static_p = S + OFF_STATIC_P;
    float* gates    = S + OFF_GATES;
    float* cp = S + OFF_CP;
    float* cq = S + OFF_CQ;
    float* rq = S + OFF_RQ;
    float* rp = S + OFF_RP;
    float* zb = S + OFF_Z;
    float* klb  = S + OFF_KLB;
    float* lpqb = S + OFF_LPQB;
    float* pw_ssm = S + OFF_PW_SSM;
    float* pw_q   = S + OFF_PW_Q;
    float* pw_p   = S + OFF_PW_P;
    float* pw_rq  = S + OFF_PW_RQ;
    float* pw_rp  = S + OFF_PW_RP;
    float* pad_C    = S + OFF_PAD_C;
    float* pad_D    = S + OFF_PAD_D;
    float* pad_a    = S + OFF_PAD_A;
    float* pad_stmo = S + OFF_PAD_STMO;
    float* pad_ztmo = S + OFF_PAD_ZTMO;
    float* pad_st   = S + OFF_PAD_ST;
    float* pad_hp   = S + OFF_PAD_HP;
    float* pad_hq   = S + OFF_PAD_HQ;
    float* pad_zb   = S + OFF_PAD_ZB;

    float* out    = (float*)d_out;
    float* out_z  = out;
    float* out_s  = out + 2097152;
    float* out_c  = out + 6291456;
    float* out_kl = out + 10485760;
    float* out_lpq= out + 10485761;

    // zero states + accumulators + ALL padded state buffers (every call!)
    cudaMemsetAsync(cp,  0, (size_t)2 * 4194304 * sizeof(float));      // cp, cq
    cudaMemsetAsync(klb, 0, 256 * sizeof(float));
    cudaMemsetAsync(pad_st, 0, (size_t)PAD_STATE_FLOATS * sizeof(float));

    // ---- combined repack (1 launch) ----
    {
        RepackJobs J;
        J.src[0] = W_ssm; J.dst[0] = pw_ssm; J.cinTot[0] = 328; J.nChunks[0] = 41;
        J.src[1] = W_q;   J.dst[1] = pw_q;   J.cinTot[1] = 520; J.nChunks[1] = 65;
        J.src[2] = W_p;   J.dst[2] = pw_p;   J.cinTot[2] = 456; J.nChunks[2] = 57;
        J.src[3] = W_rq;  J.dst[3] = pw_rq;  J.cinTot[3] = 128; J.nChunks[3] = 16;
        J.src[4] = W_rp;  J.dst[4] = pw_rp;  J.cinTot[4] = 128; J.nChunks[4] = 16;
        int tot[5] = { 8 * 41 * 12800, 8 * 65 * 12800, 8 * 57 * 12800,
                       2 * 16 * 12800, 2 * 16 * 12800 };
        J.start[0] = 0;
        for (int i = 0; i < 5; ++i) J.start[i + 1] = J.start[i] + tot[i];
        repack_all_kernel<<<(J.start[5] + 255) / 256, 256>>>(J);
    }

    // ---- combined padify (1 launch) ----
    {
        PadJobs J;
        J.src[0] = C_t;   J.dst[0] = pad_C;
        J.src[1] = D_t;   J.dst[1] = pad_D;
        J.src[2] = a_tmo; J.dst[2] = pad_a;
        J.src[3] = s_tmo; J.dst[3] = pad_stmo;
        J.src[4] = z_tmo; J.dst[4] = pad_ztmo;
        int planes[5] = { 128 * 128, 128 * 128, 128 * 8, 128 * 128, 128 * 64 };
        J.start[0] = 0;
        for (int i = 0; i < 5; ++i) J.start[i + 1] = J.start[i] + planes[i] * 640;
        padify_all_kernel<<<(J.start[5] + 255) / 256, 256>>>(J);
    }

    // ---- SSM ConvLSTM: [z_tmo 0-7, C_t 8-23, a 24, s_tmo 25-40] / 41 chunks ----
    {
        Seg segs[4] = { {pad_ztmo, 64, 0}, {pad_C, 128, 8}, {pad_a, 8, 24}, {pad_stmo, 128, 25} };
        launch_conv(segs, 4, pw_ssm, 41, b_ssm, nullptr, gates, 512);
        lstm_kernel<<<16384, 256>>>(gates, c_ssm_tmo, out_s, pad_st, out_c);
    }

    // ---- static parts ----
    {
        // q: [hp 0-15, D_t 16-31, s_t 32-47, a 48, hq 49-64]
        Seg segs[3] = { {pad_D, 128, 16}, {pad_st, 128, 32}, {pad_a, 8, 48} };
        launch_conv(segs, 3, pw_q, 65, b_q, nullptr, static_q, 512);
    }
    {
        // p: [z 0-7, C_t 8-23, s_t 24-39, a 40, hp 41-56]
        Seg segs[3] = { {pad_C, 128, 8}, {pad_st, 128, 24}, {pad_a, 8, 40} };
        launch_conv(segs, 3, pw_p, 57, b_p, nullptr, static_p, 512);
    }

    for (int t = 0; t < STEPS; ++t) {
        {
            Seg segs[2] = { {pad_hp, 128, 0}, {pad_hq, 128, 49} };
            launch_conv(segs, 2, pw_q, 65, nullptr, static_q, gates, 512);
        }
        lstm_kernel<<<16384, 256>>>(gates, cq, nullptr, pad_hq, cq);

        {
            Seg segs[1] = { {pad_hq, 128, 0} };
            launch_conv(segs, 1, pw_rq, 16, b_rq, nullptr, rq, 128);
        }
        {
            Seg segs[1] = { {pad_hp, 128, 0} };
            launch_conv(segs, 1, pw_rp, 16, b_rp, nullptr, rp, 128);
        }

        zkl_kernel<<<128, 256>>>(rq, rp, eps + (size_t)t * 2097152, zb, pad_zb, klb, lpqb);

        {
            Seg segs[2] = { {pad_zb, 64, 0}, {pad_hp, 128, 41} };
            launch_conv(segs, 2, pw_p, 57, nullptr, static_p, gates, 512);
        }
        lstm_kernel<<<16384, 256>>>(gates, cp, nullptr, pad_hp, cp);
    }

    copy_kernel<<<(2097152 + 255) / 256, 256>>>(zb, out_z, 2097152);
    finalize_kernel<<<1, 128>>>(klb, lpqb, out_kl, out_lpq);
}

// round 11
// speedup vs baseline: 1.8358x; 1.8358x over previous
#include <cuda_runtime.h>
#include <cuda_fp16.h>
#include <cstdint>
#include <math.h>

// fp16 m16n8k16 mma conv (fp32 accum), cp.async double-buffered pipeline.
#define PIX   256
#define BATCH 128
#define STEPS 6

// scratch offsets (floats)
#define OFF_STATIC_Q 0u
#define OFF_STATIC_P 16777216u
#define OFF_GATES    33554432u
#define OFF_CP       50331648u
#define OFF_CQ       54525952u
#define OFF_RQ       58720256u
#define OFF_RP       62914560u
#define OFF_Z        67108864u
#define OFF_KLB      69206016u
#define OFF_LPQB     69206144u
#define OFF_PW_SSM   69206272u
#define OFF_PW_Q     71356672u
#define OFF_PW_P     74735872u
#define OFF_PW_RQ    77705472u
#define OFF_PW_RP    77910272u
// fp16 padded planes: per (b,chunk16) = 640 pix * 12 u32 = 7680 u32 (30720 B)
#define OFF_PAD_C    78115072u
#define OFF_PAD_D    85979392u
#define OFF_PAD_A    93843712u
#define OFF_PAD_STMO 94826752u
#define OFF_PAD_ZTMO 102691072u
#define OFF_PAD_ST   106623232u
#define OFF_PAD_HP   114487552u
#define OFF_PAD_HQ   122351872u
#define OFF_PAD_ZB   130216192u
#define SCRATCH_N    134148352u
// pad_st + pad_hp + pad_hq + pad_zb (floats)
#define PAD_STATE_FLOATS 27525120u

__device__ float g_scratch[SCRATCH_N];

__device__ __forceinline__ void mma_f16(float& c0, float& c1, float& c2, float& c3,
                                        uint32_t a0, uint32_t a1, uint32_t a2, uint32_t a3,
                                        uint32_t b0, uint32_t b1) {
    asm volatile(
        "mma.sync.aligned.m16n8k16.row.col.f32.f16.f16.f32 "
        "{%0,%1,%2,%3}, {%4,%5,%6,%7}, {%8,%9}, {%0,%1,%2,%3};"
        : "+f"(c0), "+f"(c1), "+f"(c2), "+f"(c3)
        : "r"(a0), "r"(a1), "r"(a2), "r"(a3), "r"(b0), "r"(b1));
}
__device__ __forceinline__ void cpasync16(uint32_t s, const void* g) {
    asm volatile("cp.async.cg.shared.global [%0], [%1], 16;" :: "r"(s), "l"(g));
}
__device__ __forceinline__ void cpcommit() { asm volatile("cp.async.commit_group;"); }
__device__ __forceinline__ uint32_t pack_h2(float lo, float hi) {
    __half2 h = __floats2half2_rn(lo, hi);
    return *reinterpret_cast<uint32_t*>(&h);
}

// ---------------- weight repack (fp16 fragments) ----------------
// PW per (cg64, chunk16): [tap25][mp4][lane32][slot4] uint32 = 12800 u32.
struct RepackJobs {
    const float* W[5]; float* PW[5];
    int cinSrc[5], nch[5], nSeg[5];
    int segPad[5][5], segLen[5][5], segSrc[5][5];
    int start[6];
};
__device__ __forceinline__ float w_lookup(const RepackJobs& J, int j, int co, int ci, int tap) {
    int s = J.nSeg[j] - 1;
    for (int t = 1; t < J.nSeg[j]; ++t) if (ci < J.segPad[j][t]) { s = t - 1; break; }
    int off = ci - J.segPad[j][s];
    if (off >= J.segLen[j][s]) return 0.f;
    return J.W[j][((size_t)co * J.cinSrc[j] + J.segSrc[j][s] + off) * 25 + tap];
}
__global__ void repack_all_kernel(RepackJobs J) {
    int idx = blockIdx.x * 256 + threadIdx.x;
    if (idx >= J.start[5]) return;
    int j = 0; while (idx >= J.start[j + 1]) ++j;
    int L = idx - J.start[j];
    int s = L & 3, lane = (L >> 2) & 31, mp = (L >> 7) & 3;
    int rest = L >> 9;
    int tap = rest % 25, rest2 = rest / 25;
    int chunk = rest2 % J.nch[j], cg = rest2 / J.nch[j];
    int g = lane >> 2, tig = lane & 3;
    int co  = cg * 64 + mp * 16 + (s & 1) * 8 + g;
    int ci0 = chunk * 16 + 2 * tig + (s >> 1) * 8;
    reinterpret_cast<uint32_t*>(J.PW[j])[L] =
        pack_h2(w_lookup(J, j, co, ci0, tap), w_lookup(J, j, co, ci0 + 1, tap));
}

// ---------------- padify (fp16 planes) ----------------
// dst per (b,chunk): 640 pixels x 12 u32 (u0..u7 = 16 ci halves, u8..11 pad).
struct PadJobs {
    const float* src[5]; __half* dst[5];
    int cinReal[5], nch[5];
    int start[6];     // pair-index boundaries
};
__global__ void padify_all_kernel(PadJobs J) {
    int idx = blockIdx.x * 256 + threadIdx.x;
    if (idx >= J.start[5]) return;
    int j = 0; while (idx >= J.start[j + 1]) ++j;
    int L = idx - J.start[j];
    int u = L & 7;
    int pix = (L >> 3) % 640;
    int rest = L / (640 * 8);
    int ch = rest % J.nch[j], b = rest / J.nch[j];
    int row = pix >> 5, col = pix & 31;
    float v0 = 0.f, v1 = 0.f;
    if ((unsigned)(row - 2) < 16u && (unsigned)(col - 2) < 16u) {
        int ci0 = ch * 16 + 2 * u;
        int p = (row - 2) * 16 + (col - 2);
        if (ci0 < J.cinReal[j])     v0 = J.src[j][((size_t)b * J.cinReal[j] + ci0) * 256 + p];
        if (ci0 + 1 < J.cinReal[j]) v1 = J.src[j][((size_t)b * J.cinReal[j] + ci0 + 1) * 256 + p];
    }
    reinterpret_cast<uint32_t*>(J.dst[j])[((size_t)(b * J.nch[j] + ch) * 640 + pix) * 12 + u] =
        pack_h2(v0, v1);
}

// ---------------- conv ----------------
struct Seg { const __half* pad; int nch; int startChunk; };
struct ConvArgs {
    Seg seg[4]; int nseg;
    const float* PW; int nChunks;
    const float* bias; const float* base;
    float* out; int cout;
};
#define A_BYTES     51200
#define PLANE_BYTES 30720
#define BUF_BYTES   (A_BYTES + PLANE_BYTES)
#define CONV_SMEM_BYTES (2 * BUF_BYTES)   // 163840

__global__ void __launch_bounds__(256, 1) conv5x5_mma_kernel(ConvArgs a) {
    extern __shared__ char smem[];
    const int b = blockIdx.y, cg = blockIdx.x, tid = threadIdx.x;
    const int lane = tid & 31, warp = tid >> 5;
    const int tig = lane & 3, g = lane >> 2;

    int bB[4];
#pragma unroll
    for (int n = 0; n < 4; ++n) {
        int p = warp * 32 + n * 8;
        bB[n] = (p >> 4) * 32 + (p & 15) + g;
    }

    float acc[4][4][4];
#pragma unroll
    for (int m = 0; m < 4; ++m)
#pragma unroll
        for (int n = 0; n < 4; ++n)
#pragma unroll
            for (int k = 0; k < 4; ++k) acc[m][n][k] = 0.f;

    int total = 0;
    for (int s = 0; s < a.nseg; ++s) total += a.seg[s].nch;
    const uint32_t smemBase = (uint32_t)__cvta_generic_to_shared(smem);

#define ISSUE(S, C8, BI) do {                                                    \
        const uint32_t dA = smemBase + (BI) * BUF_BYTES;                         \
        const uint32_t dP = dA + A_BYTES;                                        \
        const float* pw = a.PW +                                                 \
            (size_t)(cg * a.nChunks + a.seg[S].startChunk + (C8)) * 12800;       \
        for (int j = tid; j < 3200; j += 256) cpasync16(dA + j * 16, pw + j * 4);\
        const char* sp = (const char*)a.seg[S].pad +                             \
            (size_t)(b * a.seg[S].nch + (C8)) * PLANE_BYTES;                     \
        for (int j = tid; j < 1920; j += 256) cpasync16(dP + j * 16, sp + j * 16);\
    } while (0)

    int s = 0, c8 = 0;
    ISSUE(s, c8, 0);
    cpcommit();

    for (int i = 0; i < total; ++i) {
        int sn = s, cn = c8 + 1;
        if (cn == a.seg[sn].nch) { cn = 0; ++sn; }
        if (i + 1 < total) ISSUE(sn, cn, (i + 1) & 1);
        cpcommit();
        asm volatile("cp.async.wait_group 1;");
        __syncthreads();

        const char* bufc = smem + (i & 1) * BUF_BYTES;
        const char* aB   = bufc + lane * 16;
        const char* plc  = bufc + A_BYTES + tig * 4;

#pragma unroll
        for (int dy = 0; dy < 5; ++dy) {
#pragma unroll
            for (int dx = 0; dx < 5; ++dx) {
                const int tap = dy * 5 + dx;
                uint4 A[4];
#pragma unroll
                for (int mp = 0; mp < 4; ++mp)
                    A[mp] = *(const uint4*)(aB + tap * 2048 + mp * 512);
                const int toff = dy * 1536 + dx * 48;
#pragma unroll
                for (int n = 0; n < 4; ++n) {
                    const char* bp = plc + bB[n] * 48 + toff;
                    const uint32_t b0 = *(const uint32_t*)bp;
                    const uint32_t b1 = *(const uint32_t*)(bp + 16);
#pragma unroll
                    for (int mp = 0; mp < 4; ++mp)
                        mma_f16(acc[mp][n][0], acc[mp][n][1], acc[mp][n][2], acc[mp][n][3],
                                A[mp].x, A[mp].y, A[mp].z, A[mp].w, b0, b1);
                }
            }
        }
        __syncthreads();
        s = sn; c8 = cn;
    }
#undef ISSUE

    const int coBase = cg * 64;
#pragma unroll
    for (int mp = 0; mp < 4; ++mp) {
        const int row0 = coBase + mp * 16 + g;
        const int row1 = row0 + 8;
        const float bias0 = a.bias ? a.bias[row0] : 0.f;
        const float bias1 = a.bias ? a.bias[row1] : 0.f;
#pragma unroll
        for (int n = 0; n < 4; ++n) {
            const int col = warp * 32 + n * 8 + 2 * tig;
            size_t o0 = ((size_t)b * a.cout + row0) * PIX + col;
            size_t o1 = ((size_t)b * a.cout + row1) * PIX + col;
            float v0 = acc[mp][n][0] + bias0;
            float v1 = acc[mp][n][1] + bias0;
            float v2 = acc[mp][n][2] + bias1;
            float v3 = acc[mp][n][3] + bias1;
            if (a.base) {
                v0 += a.base[o0]; v1 += a.base[o0 + 1];
                v2 += a.base[o1]; v3 += a.base[o1 + 1];
            }
            a.out[o0] = v0; a.out[o0 + 1] = v1;
            a.out[o1] = v2; a.out[o1 + 1] = v3;
        }
    }
}

// ---------------- pointwise ----------------
__device__ __forceinline__ float sigmoidf_(float x) { return 1.f / (1.f + expf(-x)); }

// h_pad fp16 planes: [b][nchPad=8][640 pix][24 halves]
__global__ void lstm_kernel(const float* __restrict__ gates,
                            const float* __restrict__ c_in,
                            float* __restrict__ h_exact,
                            __half* __restrict__ h_pad,
                            float* __restrict__ c_out) {
    int idx = blockIdx.x * blockDim.x + threadIdx.x;
    if (idx >= 4194304) return;
    int b = idx >> 15;
    int r = idx & 32767;
    size_t g0 = (size_t)b * 131072 + r;
    float ig = gates[g0];
    float fg = gates[g0 + 32768];
    float og = gates[g0 + 65536];
    float gg = gates[g0 + 98304];
    float c  = sigmoidf_(fg) * c_in[idx] + sigmoidf_(ig) * tanhf(gg);
    c_out[idx] = c;
    float h = sigmoidf_(og) * tanhf(c);
    if (h_exact) h_exact[idx] = h;
    int ch = r >> 8, pix = r & 255;
    int pp = ((pix >> 4) + 2) * 32 + (pix & 15) + 2;
    h_pad[((size_t)(b * 8 + (ch >> 4)) * 640 + pp) * 24 + (ch & 15)] = __float2half_rn(h);
}

__global__ void zkl_kernel(const float* __restrict__ rq,
                           const float* __restrict__ rp,
                           const float* __restrict__ eps_t,
                           float* __restrict__ z,
                           __half* __restrict__ z_pad,
                           float* __restrict__ klb,
                           float* __restrict__ lpqb) {
    const int b = blockIdx.x;
    const int tid = threadIdx.x;
    const float* rqb = rq + (size_t)b * 32768;
    const float* rpb = rp + (size_t)b * 32768;
    const float* eb  = eps_t + (size_t)b * 16384;
    float* zb = z + (size_t)b * 16384;

    float kl = 0.f, lpq = 0.f;
    for (int i = tid; i < 16384; i += 256) {
        float mq = rqb[i], lq = rqb[i + 16384];
        float mp = rpb[i], lp = rpb[i + 16384];
        float e  = eb[i];
        float zi = mq + expf(0.5f * lq) * e;
        zb[i] = zi;
        int ch = i >> 8, pix = i & 255;
        int pp = ((pix >> 4) + 2) * 32 + (pix & 15) + 2;
        z_pad[((size_t)(b * 4 + (ch >> 4)) * 640 + pp) * 24 + (ch & 15)] = __float2half_rn(zi);
        float dq = zi - mq, dp = zi - mp;
        lpq += 0.5f * ((lq + dq * dq * expf(-lq)) - (lp + dp * dp * expf(-lp)));
        float dm = mq - mp;
        kl  += 0.5f * (lp - lq + (expf(lq) + dm * dm) * expf(-lp) - 1.f);
    }
    __shared__ float s1[256], s2[256];
    s1[tid] = kl; s2[tid] = lpq;
    __syncthreads();
    for (int o = 128; o > 0; o >>= 1) {
        if (tid < o) { s1[tid] += s1[tid + o]; s2[tid] += s2[tid + o]; }
        __syncthreads();
    }
    if (tid == 0) { klb[b] += s1[0]; lpqb[b] += s2[0]; }
}

__global__ void copy_kernel(const float* __restrict__ src, float* __restrict__ dst, int n) {
    int i = blockIdx.x * blockDim.x + threadIdx.x;
    if (i < n) dst[i] = src[i];
}

__global__ void finalize_kernel(const float* __restrict__ klb,
                                const float* __restrict__ lpqb,
                                float* __restrict__ out_kl,
                                float* __restrict__ out_lpq) {
    __shared__ float s[128];
    int t = threadIdx.x;
    s[t] = klb[t];
    out_lpq[t] = lpqb[t];
    __syncthreads();
    for (int o = 64; o > 0; o >>= 1) {
        if (t < o) s[t] += s[t + o];
        __syncthreads();
    }
    if (t == 0) out_kl[0] = s[0] / 128.f;
}

// ---------------------------------------------------------------------------
static void launch_conv(const Seg* segs, int nseg, const float* PW, int nChunks,
                        const float* bias, const float* base, float* out, int cout) {
    ConvArgs a;
    for (int i = 0; i < 4; ++i) { a.seg[i].pad = nullptr; a.seg[i].nch = 0; a.seg[i].startChunk = 0; }
    for (int i = 0; i < nseg; ++i) a.seg[i] = segs[i];
    a.nseg = nseg; a.PW = PW; a.nChunks = nChunks;
    a.bias = bias; a.base = base; a.out = out; a.cout = cout;
    dim3 grid(cout / 64, BATCH);
    conv5x5_mma_kernel<<<grid, 256, CONV_SMEM_BYTES>>>(a);
}

extern "C" void kernel_launch(void* const* d_in, const int* in_sizes, int n_in,
                              void* d_out, int out_size) {
    (void)in_sizes; (void)n_in; (void)out_size;
    const float* C_t    = (const float*)d_in[0];
    const float* D_t    = (const float*)d_in[1];
    const float* a_tmo  = (const float*)d_in[2];
    const float* s_tmo  = (const float*)d_in[3];
    const float* c_ssm_tmo = (const float*)d_in[4];
    const float* z_tmo  = (const float*)d_in[5];
    const float* eps    = (const float*)d_in[6];
    const float* W_ssm  = (const float*)d_in[7];
    const float* b_ssm  = (const float*)d_in[8];
    const float* W_p    = (const float*)d_in[9];
    const float* b_p    = (const float*)d_in[10];
    const float* W_q    = (const float*)d_in[11];
    const float* b_q    = (const float*)d_in[12];
    const float* W_rp   = (const float*)d_in[13];
    const float* b_rp   = (const float*)d_in[14];
    const float* W_rq   = (const float*)d_in[15];
    const float* b_rq   = (const float*)d_in[16];

    static int smem_set = -1;
    if (smem_set < 0) {
        cudaFuncSetAttribute(conv5x5_mma_kernel,
                             cudaFuncAttributeMaxDynamicSharedMemorySize, CONV_SMEM_BYTES);
        smem_set = 1;
    }

    float* S;
    cudaGetSymbolAddress((void**)&S, g_scratch);
    float* static_q = S + OFF_STATIC_Q;
    float* static_p = S + OFF_STATIC_P;
    float* gates    = S + OFF_GATES;
    float* cp = S + OFF_CP;
    float* cq = S + OFF_CQ;
    float* rq = S + OFF_RQ;
    float* rp = S + OFF_RP;
    float* zb = S + OFF_Z;
    float* klb  = S + OFF_KLB;
    float* lpqb = S + OFF_LPQB;
    float* pw_ssm = S + OFF_PW_SSM;
    float* pw_q   = S + OFF_PW_Q;
    float* pw_p   = S + OFF_PW_P;
    float* pw_rq  = S + OFF_PW_RQ;
    float* pw_rp  = S + OFF_PW_RP;
    __half* pad_C    = (__half*)(S + OFF_PAD_C);
    __half* pad_D    = (__half*)(S + OFF_PAD_D);
    __half* pad_a    = (__half*)(S + OFF_PAD_A);
    __half* pad_stmo = (__half*)(S + OFF_PAD_STMO);
    __half* pad_ztmo = (__half*)(S + OFF_PAD_ZTMO);
    __half* pad_st   = (__half*)(S + OFF_PAD_ST);
    __half* pad_hp   = (__half*)(S + OFF_PAD_HP);
    __half* pad_hq   = (__half*)(S + OFF_PAD_HQ);
    __half* pad_zb   = (__half*)(S + OFF_PAD_ZB);

    float* out    = (float*)d_out;
    float* out_z  = out;
    float* out_s  = out + 2097152;
    float* out_c  = out + 6291456;
    float* out_kl = out + 10485760;
    float* out_lpq= out + 10485761;

    // per-call zeroing: states + accumulators + padded state planes
    cudaMemsetAsync(cp,  0, (size_t)2 * 4194304 * sizeof(float));
    cudaMemsetAsync(klb, 0, 256 * sizeof(float));
    cudaMemsetAsync(pad_st, 0, (size_t)PAD_STATE_FLOATS * sizeof(float));

    // ---- combined repack ----
    {
        RepackJobs J;
        // ssm: z[0,64)->0, C[64,192)->64, a[192,208)len8->192, s[208,336)->200
        J.W[0]=W_ssm; J.PW[0]=pw_ssm; J.cinSrc[0]=328; J.nch[0]=21; J.nSeg[0]=4;
        int sp0[4]={0,64,192,208}, sl0[4]={64,128,8,128}, ss0[4]={0,64,192,200};
        // q: hp0, D128, s256, a384(len8), hq400->src392
        J.W[1]=W_q; J.PW[1]=pw_q; J.cinSrc[1]=520; J.nch[1]=33; J.nSeg[1]=5;
        int sp1[5]={0,128,256,384,400}, sl1[5]={128,128,128,8,128}, ss1[5]={0,128,256,384,392};
        // p: z0(64), C64, s192, a320(8), hp336->src328
        J.W[2]=W_p; J.PW[2]=pw_p; J.cinSrc[2]=456; J.nch[2]=29; J.nSeg[2]=5;
        int sp2[5]={0,64,192,320,336}, sl2[5]={64,128,128,8,128}, ss2[5]={0,64,192,320,328};
        J.W[3]=W_rq; J.PW[3]=pw_rq; J.cinSrc[3]=128; J.nch[3]=8; J.nSeg[3]=1;
        J.W[4]=W_rp; J.PW[4]=pw_rp; J.cinSrc[4]=128; J.nch[4]=8; J.nSeg[4]=1;
        for (int k = 0; k < 4; ++k) { J.segPad[0][k]=sp0[k]; J.segLen[0][k]=sl0[k]; J.segSrc[0][k]=ss0[k]; }
        for (int k = 0; k < 5; ++k) { J.segPad[1][k]=sp1[k]; J.segLen[1][k]=sl1[k]; J.segSrc[1][k]=ss1[k]; }
        for (int k = 0; k < 5; ++k) { J.segPad[2][k]=sp2[k]; J.segLen[2][k]=sl2[k]; J.segSrc[2][k]=ss2[k]; }
        J.segPad[3][0]=0; J.segLen[3][0]=128; J.segSrc[3][0]=0;
        J.segPad[4][0]=0; J.segLen[4][0]=128; J.segSrc[4][0]=0;
        int cgs[5] = {8, 8, 8, 2, 2};
        J.start[0] = 0;
        for (int i = 0; i < 5; ++i) J.start[i + 1] = J.start[i] + cgs[i] * J.nch[i] * 12800;
        repack_all_kernel<<<(J.start[5] + 255) / 256, 256>>>(J);
    }

    // ---- combined padify ----
    {
        PadJobs J;
        J.src[0]=C_t;   J.dst[0]=pad_C;    J.cinReal[0]=128; J.nch[0]=8;
        J.src[1]=D_t;   J.dst[1]=pad_D;    J.cinReal[1]=128; J.nch[1]=8;
        J.src[2]=a_tmo; J.dst[2]=pad_a;    J.cinReal[2]=8;   J.nch[2]=1;
        J.src[3]=s_tmo; J.dst[3]=pad_stmo; J.cinReal[3]=128; J.nch[3]=8;
        J.src[4]=z_tmo; J.dst[4]=pad_ztmo; J.cinReal[4]=64;  J.nch[4]=4;
        J.start[0] = 0;
        for (int i = 0; i < 5; ++i) J.start[i + 1] = J.start[i] + BATCH * J.nch[i] * 640 * 8;
        padify_all_kernel<<<(J.start[5] + 255) / 256, 256>>>(J);
    }

    // ---- SSM conv: chunks z 0-3, C 4-11, a 12, s 13-20 (nChunks 21) ----
    {
        Seg segs[4] = { {pad_ztmo,4,0}, {pad_C,8,4}, {pad_a,1,12}, {pad_stmo,8,13} };
        launch_conv(segs, 4, pw_ssm, 21, b_ssm, nullptr, gates, 512);
        lstm_kernel<<<16384, 256>>>(gates, c_ssm_tmo, out_s, pad_st, out_c);
    }
    // ---- static q: D 8-15, s_t 16-23, a 24  (q chunks: hp 0-7, hq 25-32; nChunks 33) ----
    {
        Seg segs[3] = { {pad_D,8,8}, {pad_st,8,16}, {pad_a,1,24} };
        launch_conv(segs, 3, pw_q, 33, b_q, nullptr, static_q, 512);
    }
    // ---- static p: C 4-11, s_t 12-19, a 20 (p chunks: z 0-3, hp 21-28; nChunks 29) ----
    {
        Seg segs[3] = { {pad_C,8,4}, {pad_st,8,12}, {pad_a,1,20} };
        launch_conv(segs, 3, pw_p, 29, b_p, nullptr, static_p, 512);
    }

    for (int t = 0; t < STEPS; ++t) {
        {
            Seg segs[2] = { {pad_hp,8,0}, {pad_hq,8,25} };
            launch_conv(segs, 2, pw_q, 33, nullptr, static_q, gates, 512);
        }
        lstm_kernel<<<16384, 256>>>(gates, cq, nullptr, pad_hq, cq);

        {
            Seg segs[1] = { {pad_hq,8,0} };
            launch_conv(segs, 1, pw_rq, 8, b_rq, nullptr, rq, 128);
        }
        {
            Seg segs[1] = { {pad_hp,8,0} };
            launch_conv(segs, 1, pw_rp, 8, b_rp, nullptr, rp, 128);
        }

        zkl_kernel<<<128, 256>>>(rq, rp, eps + (size_t)t * 2097152, zb, pad_zb, klb, lpqb);

        {
            Seg segs[2] = { {pad_zb,4,0}, {pad_hp,8,21} };
            launch_conv(segs, 2, pw_p, 29, nullptr, static_p, gates, 512);
        }
        lstm_kernel<<<16384, 256>>>(gates, cp, nullptr, pad_hp, cp);
    }

    copy_kernel<<<(2097152 + 255) / 256, 256>>>(zb, out_z, 2097152);
    finalize_kernel<<<1, 128>>>(klb, lpqb, out_kl, out_lpq);
}